// round 3
// baseline (speedup 1.0000x reference)
#include <cuda_runtime.h>
#include <math.h>

#define NN 384
#define RR 128
#define KK 4
#define JJ 512   // K*R
#define GG 5
#define OO 2

#define PI_OFF  0
#define MU_OFF  (NN*GG)              // 1920
#define SIG_OFF (MU_OFF + NN*GG*OO)  // 5760
#define H_OFF   (SIG_OFF + NN*GG*OO) // 9600
#define C_OFF   (H_OFF + NN*RR)      // 58752

// Scratch (no allocations allowed)
__device__ float g_P[NN*JJ];      // P[m][j] = dot(W_loc[j], nodes[m])
__device__ float g_X[NN*RR];      // x = relu(nodes[:,:4]@W_in^T + b_in) + social
__device__ float g_WT[256*JJ];    // transposed [X|H] weights: row k, col j
__device__ float g_Wmsum[KK];     // sum_r W_mode[r,k]
__device__ float g_bmsum[1];      // sum_r b_mode[r]

// ---------------------------------------------------------------------------
// K1: P[m][j] = dot6(W_loc[j], nodes[m]); 8 nodes per block (amortize W_loc).
// Block 0 also reduces W_mode/b_mode sums.
// ---------------------------------------------------------------------------
__global__ void __launch_bounds__(512) k_pre(
    const float* __restrict__ nodes, const float* __restrict__ W_loc,
    const float* __restrict__ W_mode, const float* __restrict__ b_mode)
{
    int j = threadIdx.x;
    int m0 = blockIdx.x * 8;
    __shared__ float nd[8][6];
    if (j < 48) nd[j/6][j%6] = nodes[m0*6 + j];
    const float* w = W_loc + j*6;
    float w0 = w[0], w1 = w[1], w2 = w[2], w3 = w[3], w4 = w[4], w5 = w[5];
    __syncthreads();
    #pragma unroll
    for (int mm = 0; mm < 8; mm++) {
        g_P[(m0+mm)*JJ + j] = w0*nd[mm][0] + w1*nd[mm][1] + w2*nd[mm][2]
                            + w3*nd[mm][3] + w4*nd[mm][4] + w5*nd[mm][5];
    }

    if (blockIdx.x == 0 && j < 32) {
        float sk0=0.f, sk1=0.f, sk2=0.f, sk3=0.f, sbm=0.f;
        for (int r = j; r < RR; r += 32) {
            sk0 += W_mode[r*4+0];
            sk1 += W_mode[r*4+1];
            sk2 += W_mode[r*4+2];
            sk3 += W_mode[r*4+3];
            sbm += b_mode[r];
        }
        #pragma unroll
        for (int o = 16; o > 0; o >>= 1) {
            sk0 += __shfl_down_sync(0xffffffffu, sk0, o);
            sk1 += __shfl_down_sync(0xffffffffu, sk1, o);
            sk2 += __shfl_down_sync(0xffffffffu, sk2, o);
            sk3 += __shfl_down_sync(0xffffffffu, sk3, o);
            sbm += __shfl_down_sync(0xffffffffu, sbm, o);
        }
        if (j == 0) {
            g_Wmsum[0] = sk0; g_Wmsum[1] = sk1;
            g_Wmsum[2] = sk2; g_Wmsum[3] = sk3;
            g_bmsum[0] = sbm;
        }
    }
}

// ---------------------------------------------------------------------------
// K1b: transpose W_ih / W_hh into g_WT[k][j]  (k<128 -> W_ih, else W_hh).
// ---------------------------------------------------------------------------
__global__ void __launch_bounds__(256) k_wt(
    const float* __restrict__ W_ih, const float* __restrict__ W_hh)
{
    __shared__ float tile[32][33];
    int jb = blockIdx.x * 32;          // gridDim.x = 16
    int rb = blockIdx.y * 32;          // gridDim.y = 4
    const float* W = blockIdx.z ? W_hh : W_ih;
    int tx = threadIdx.x & 31;
    int ty = threadIdx.x >> 5;         // 0..7
    #pragma unroll
    for (int u = 0; u < 32; u += 8)
        tile[ty+u][tx] = W[(jb+ty+u)*RR + rb + tx];
    __syncthreads();
    int kbase = rb + blockIdx.z * RR;
    #pragma unroll
    for (int u = 0; u < 32; u += 8)
        g_WT[(kbase+ty+u)*JJ + jb + tx] = tile[tx][ty+u];
}

// ---------------------------------------------------------------------------
// K2: social attention, one block per node n.
// ---------------------------------------------------------------------------
__global__ void __launch_bounds__(256) k_social(
    const float* __restrict__ nodes, const int* __restrict__ visible,
    const float* __restrict__ h_in,  const float* __restrict__ b_loc,
    const float* __restrict__ W_score, const float* __restrict__ b_score,
    const float* __restrict__ W_mode,  const float* __restrict__ b_mode,
    const float* __restrict__ W_in,    const float* __restrict__ b_in)
{
    int n = blockIdx.x;
    int t = threadIdx.x;
    int lane = t & 31;
    int wrp  = t >> 5;

    __shared__ __align__(16) float sPn[JJ];
    __shared__ __align__(16) float sb[JJ];
    __shared__ float shs[RR];
    __shared__ float ssv[NN];
    __shared__ float sal[NN];
    __shared__ int   skh[NN];    // -1 => invisible
    __shared__ float scoef[NN];  // w_i * alpha_i
    __shared__ float sred[8*5];
    __shared__ float sm4[KK], sden[KK], sSk[KK];
    __shared__ float sWtot;
    __shared__ float sscal[8];   // [0]=b_score, [1..4]=Wmsum, [5]=bmsum
    __shared__ float snd[6];
    __shared__ float sChalf[RR];

    sPn[t]      = g_P[n*JJ + t];
    sPn[t+256]  = g_P[n*JJ + 256 + t];
    sb[t]       = b_loc[t];
    sb[t+256]   = b_loc[256 + t];
    if (t < RR) shs[t] = h_in[n*RR + t] * W_score[t];
    if (t == 0) sscal[0] = b_score[0];
    if (t < 4)  sscal[1+t] = g_Wmsum[t];
    if (t == 4) sscal[5] = g_bmsum[0];
    if (t < 6)  snd[t] = nodes[n*6 + t];
    __syncthreads();

    // --- Phase A: 4 pairs per warp, 8 lanes per pair, full 128-float4 range ---
    {
        int p   = lane >> 3;   // pair within warp (0..3)
        int sub = lane & 7;    // lane within pair
        const float4* Pn4 = (const float4*)sPn;
        const float4* B4  = (const float4*)sb;
        #pragma unroll 1
        for (int it = 0; it < 12; it++) {
            int i = it*32 + wrp*4 + p;
            const float4* Pi = (const float4*)(g_P + i*JJ);
            float s0=0.f,s1=0.f,s2=0.f,s3=0.f, L0=0.f,L1=0.f,L2=0.f,L3=0.f;
            #pragma unroll
            for (int u = 0; u < 16; u++) {
                int r = sub + 8*u;
                float4 pi4 = Pi[r];
                float4 pn4 = Pn4[r];
                float4 b4  = B4[r];
                float hv = shs[r];
                float l0 = fmaxf(pn4.x - pi4.x + b4.x, 0.f);
                float l1 = fmaxf(pn4.y - pi4.y + b4.y, 0.f);
                float l2 = fmaxf(pn4.z - pi4.z + b4.z, 0.f);
                float l3 = fmaxf(pn4.w - pi4.w + b4.w, 0.f);
                s0 += l0*hv; s1 += l1*hv; s2 += l2*hv; s3 += l3*hv;
                L0 += l0; L1 += l1; L2 += l2; L3 += l3;
            }
            #pragma unroll
            for (int o = 4; o > 0; o >>= 1) {
                s0 += __shfl_xor_sync(0xffffffffu, s0, o);
                s1 += __shfl_xor_sync(0xffffffffu, s1, o);
                s2 += __shfl_xor_sync(0xffffffffu, s2, o);
                s3 += __shfl_xor_sync(0xffffffffu, s3, o);
                L0 += __shfl_xor_sync(0xffffffffu, L0, o);
                L1 += __shfl_xor_sync(0xffffffffu, L1, o);
                L2 += __shfl_xor_sync(0xffffffffu, L2, o);
                L3 += __shfl_xor_sync(0xffffffffu, L3, o);
            }
            if (sub == 0) {
                float bs = sscal[0];
                s0 += bs; s1 += bs; s2 += bs; s3 += bs;
                int kh = 0; float smx = s0;
                if (s1 > smx) { smx = s1; kh = 1; }
                if (s2 > smx) { smx = s2; kh = 2; }
                if (s3 > smx) { smx = s3; kh = 3; }
                float e0 = __expf(s0 - smx), e1 = __expf(s1 - smx);
                float e2 = __expf(s2 - smx), e3 = __expf(s3 - smx);
                float soft = 1.0f / (e0 + e1 + e2 + e3);   // soft at khat
                float alpha = (1.0f - soft) + soft;        // straight-through
                float Lh = (kh==0) ? L0 : (kh==1) ? L1 : (kh==2) ? L2 : L3;
                float sv = alpha*Lh + (alpha*sscal[1+kh] + sscal[5]);
                int vis = visible[n*NN + i];
                skh[i] = (vis > 0) ? kh : -1;
                sal[i] = alpha;
                ssv[i] = sv;
            }
        }
    }
    __syncthreads();

    // --- Phase B: per-head masked softmax over neighbors ---
    {
        float m0=-3.0e38f, m1=-3.0e38f, m2=-3.0e38f, m3=-3.0e38f;
        for (int i = t; i < NN; i += 256) {
            int kh = skh[i];
            float v = ssv[i];
            if (kh == 0) m0 = fmaxf(m0, v);
            else if (kh == 1) m1 = fmaxf(m1, v);
            else if (kh == 2) m2 = fmaxf(m2, v);
            else if (kh == 3) m3 = fmaxf(m3, v);
        }
        #pragma unroll
        for (int o = 16; o > 0; o >>= 1) {
            m0 = fmaxf(m0, __shfl_xor_sync(0xffffffffu, m0, o));
            m1 = fmaxf(m1, __shfl_xor_sync(0xffffffffu, m1, o));
            m2 = fmaxf(m2, __shfl_xor_sync(0xffffffffu, m2, o));
            m3 = fmaxf(m3, __shfl_xor_sync(0xffffffffu, m3, o));
        }
        if (lane == 0) {
            sred[wrp*4+0]=m0; sred[wrp*4+1]=m1; sred[wrp*4+2]=m2; sred[wrp*4+3]=m3;
        }
        __syncthreads();
        if (t < 4) {
            float m = sred[t];
            for (int ww = 1; ww < 8; ww++) m = fmaxf(m, sred[ww*4+t]);
            sm4[t] = m;
        }
        __syncthreads();
    }
    {
        float d0=0.f, d1=0.f, d2=0.f, d3=0.f;
        for (int i = t; i < NN; i += 256) {
            int kh = skh[i];
            if (kh >= 0) {
                float e = __expf(ssv[i] - sm4[kh]);
                if (kh == 0) d0 += e;
                else if (kh == 1) d1 += e;
                else if (kh == 2) d2 += e;
                else d3 += e;
            }
        }
        #pragma unroll
        for (int o = 16; o > 0; o >>= 1) {
            d0 += __shfl_xor_sync(0xffffffffu, d0, o);
            d1 += __shfl_xor_sync(0xffffffffu, d1, o);
            d2 += __shfl_xor_sync(0xffffffffu, d2, o);
            d3 += __shfl_xor_sync(0xffffffffu, d3, o);
        }
        if (lane == 0) {
            sred[wrp*4+0]=d0; sred[wrp*4+1]=d1; sred[wrp*4+2]=d2; sred[wrp*4+3]=d3;
        }
        __syncthreads();
        if (t < 4) {
            float d = 0.f;
            for (int ww = 0; ww < 8; ww++) d += sred[ww*4+t];
            sden[t] = d;
        }
        __syncthreads();
    }
    {
        float k0=0.f, k1=0.f, k2=0.f, k3=0.f, wt=0.f;
        for (int i = t; i < NN; i += 256) {
            int kh = skh[i];
            float c = 0.f;
            if (kh >= 0) {
                float wv = __expf(ssv[i] - sm4[kh]) / sden[kh];
                c = wv * sal[i];
                wt += wv;
                if (kh == 0) k0 += c;
                else if (kh == 1) k1 += c;
                else if (kh == 2) k2 += c;
                else k3 += c;
            }
            scoef[i] = c;
        }
        #pragma unroll
        for (int o = 16; o > 0; o >>= 1) {
            k0 += __shfl_xor_sync(0xffffffffu, k0, o);
            k1 += __shfl_xor_sync(0xffffffffu, k1, o);
            k2 += __shfl_xor_sync(0xffffffffu, k2, o);
            k3 += __shfl_xor_sync(0xffffffffu, k3, o);
            wt += __shfl_xor_sync(0xffffffffu, wt, o);
        }
        if (lane == 0) {
            sred[wrp*5+0]=k0; sred[wrp*5+1]=k1; sred[wrp*5+2]=k2;
            sred[wrp*5+3]=k3; sred[wrp*5+4]=wt;
        }
        __syncthreads();
        if (t < 5) {
            float s = 0.f;
            for (int ww = 0; ww < 8; ww++) s += sred[ww*5+t];
            if (t < 4) sSk[t] = s; else sWtot = s;
        }
        __syncthreads();
    }

    // --- Phase C: social[n][r] accumulation + x ---
    {
        int r = t & 127;
        int half = t >> 7;
        float acc = 0.f;
        int i0 = half * 192;
        for (int i = i0; i < i0 + 192; i++) {
            int kh = skh[i];
            float c = scoef[i];
            if (kh >= 0 && c != 0.f) {
                int j = r*4 + kh;
                acc += c * fmaxf(sPn[j] - g_P[i*JJ + j] + sb[j], 0.f);
            }
        }
        if (half == 1) sChalf[r] = acc;
        __syncthreads();
        if (half == 0) {
            acc += sChalf[r];
            float soc = acc
                + sSk[0]*W_mode[r*4+0] + sSk[1]*W_mode[r*4+1]
                + sSk[2]*W_mode[r*4+2] + sSk[3]*W_mode[r*4+3]
                + sWtot * b_mode[r];
            const float* wi = W_in + r*4;
            float xr = fmaxf(wi[0]*snd[0] + wi[1]*snd[1] + wi[2]*snd[2]
                             + wi[3]*snd[3] + b_in[r], 0.f) + soc;
            g_X[n*RR + r] = xr;
        }
    }
}

// ---------------------------------------------------------------------------
// K3: LSTM cell as GEMM with transposed weights + MDN heads. 4 nodes/block.
// ---------------------------------------------------------------------------
__device__ __forceinline__ float sigf(float x) { return 1.f / (1.f + __expf(-x)); }

#define BN 4
__global__ void __launch_bounds__(256) k_lstm(
    const float* __restrict__ h_in, const float* __restrict__ c_in,
    const float* __restrict__ b_ih, const float* __restrict__ b_hh,
    const float* __restrict__ W_pi, const float* __restrict__ b_pi,
    const float* __restrict__ W_mu, const float* __restrict__ b_mu,
    const float* __restrict__ W_sig, const float* __restrict__ b_sig,
    float* __restrict__ out)
{
    int n0 = blockIdx.x * BN;
    int t = threadIdx.x;

    __shared__ float sA[BN][256];   // [nn][k] : X (k<128) then H
    __shared__ float sG[BN][JJ];
    __shared__ float sW[25*RR];
    __shared__ float sh[BN][RR];
    __shared__ float sLg[BN][25];

    for (int e = t; e < BN*RR; e += 256) {
        int nn = e >> 7, r = e & 127;
        sA[nn][r]     = g_X[(n0+nn)*RR + r];
        sA[nn][128+r] = h_in[(n0+nn)*RR + r];
    }
    for (int e = t; e < 25*RR; e += 256) {
        float v = (e < 640) ? W_pi[e] : (e < 1920) ? W_mu[e-640] : W_sig[e-1920];
        sW[e] = v;
    }
    __syncthreads();

    // gates for columns j0=2t, j1=2t+1 over all 4 nodes
    int j0 = 2*t, j1 = 2*t + 1;
    float a0[BN] = {0.f,0.f,0.f,0.f};
    float a1[BN] = {0.f,0.f,0.f,0.f};
    const float2* WT2 = (const float2*)g_WT;
    #pragma unroll 4
    for (int k = 0; k < 256; k++) {
        float2 w = WT2[k*256 + t];
        #pragma unroll
        for (int nn = 0; nn < BN; nn++) {
            float a = sA[nn][k];
            a0[nn] += a * w.x;
            a1[nn] += a * w.y;
        }
    }
    float bb0 = b_ih[j0] + b_hh[j0];
    float bb1 = b_ih[j1] + b_hh[j1];
    #pragma unroll
    for (int nn = 0; nn < BN; nn++) {
        sG[nn][j0] = a0[nn] + bb0;
        sG[nn][j1] = a1[nn] + bb1;
    }
    __syncthreads();

    // LSTM combine; write h,c
    for (int e = t; e < BN*RR; e += 256) {
        int nn = e >> 7, r = e & 127;
        float gi = sG[nn][r];
        float gf = sG[nn][RR + r];
        float gg = sG[nn][2*RR + r];
        float go = sG[nn][3*RR + r];
        float cp = c_in[(n0+nn)*RR + r];
        float c = sigf(gf)*cp + sigf(gi)*tanhf(gg);
        float h = sigf(go)*tanhf(c);
        out[C_OFF + (n0+nn)*RR + r] = c;
        out[H_OFF + (n0+nn)*RR + r] = h;
        sh[nn][r] = h;
    }
    __syncthreads();

    // heads: 25 dot products per node
    if (t < BN*25) {
        int nn = t / 25, q = t % 25;
        const float* wr = sW + q*RR;
        float acc = 0.f;
        #pragma unroll 4
        for (int r = 0; r < RR; r++) acc += wr[r] * sh[nn][r];
        sLg[nn][q] = acc;
    }
    __syncthreads();

    if (t < BN) {  // pi softmax
        int nn = t;
        float l[GG];
        float m = -3.0e38f;
        #pragma unroll
        for (int g = 0; g < GG; g++) { l[g] = sLg[nn][g] + b_pi[g]; m = fmaxf(m, l[g]); }
        float s = 0.f;
        #pragma unroll
        for (int g = 0; g < GG; g++) { l[g] = __expf(l[g] - m); s += l[g]; }
        float inv = 1.f / s;
        #pragma unroll
        for (int g = 0; g < GG; g++)
            out[PI_OFF + (n0+nn)*GG + g] = l[g] * inv;
    }
    if (t >= 32 && t < 32 + BN*10) {  // mu
        int idx = t - 32;
        int nn = idx / 10, q = idx % 10;
        out[MU_OFF + (n0+nn)*10 + q] = sLg[nn][5+q] + b_mu[q];
    }
    if (t >= 96 && t < 96 + BN*10) {  // sigma
        int idx = t - 96;
        int nn = idx / 10, q = idx % 10;
        out[SIG_OFF + (n0+nn)*10 + q] = __expf(sLg[nn][15+q] + b_sig[q]);
    }
}

// ---------------------------------------------------------------------------
extern "C" void kernel_launch(void* const* d_in, const int* in_sizes, int n_in,
                              void* d_out, int out_size)
{
    const float* nodes   = (const float*)d_in[0];
    const int*   visible = (const int*)  d_in[1];
    const float* h_in    = (const float*)d_in[2];
    const float* c_in    = (const float*)d_in[3];
    const float* W_loc   = (const float*)d_in[4];
    const float* b_loc   = (const float*)d_in[5];
    const float* W_score = (const float*)d_in[6];
    const float* b_score = (const float*)d_in[7];
    const float* W_mode  = (const float*)d_in[8];
    const float* b_mode  = (const float*)d_in[9];
    const float* W_in    = (const float*)d_in[10];
    const float* b_in    = (const float*)d_in[11];
    const float* W_ih    = (const float*)d_in[12];
    const float* W_hh    = (const float*)d_in[13];
    const float* b_ih    = (const float*)d_in[14];
    const float* b_hh    = (const float*)d_in[15];
    const float* W_pi    = (const float*)d_in[16];
    const float* b_pi    = (const float*)d_in[17];
    const float* W_mu    = (const float*)d_in[18];
    const float* b_mu    = (const float*)d_in[19];
    const float* W_sig   = (const float*)d_in[20];
    const float* b_sig   = (const float*)d_in[21];
    float* out = (float*)d_out;

    k_pre<<<NN/8, 512>>>(nodes, W_loc, W_mode, b_mode);
    dim3 wt_grid(16, 4, 2);
    k_wt<<<wt_grid, 256>>>(W_ih, W_hh);
    k_social<<<NN, 256>>>(nodes, visible, h_in, b_loc, W_score, b_score,
                          W_mode, b_mode, W_in, b_in);
    k_lstm<<<NN/BN, 256>>>(h_in, c_in, b_ih, b_hh,
                           W_pi, b_pi, W_mu, b_mu, W_sig, b_sig, out);
}

// round 5
// speedup vs baseline: 1.6115x; 1.6115x over previous
#include <cuda_runtime.h>
#include <math.h>

#define NN 384
#define RR 128
#define KK 4
#define JJ 512   // K*R
#define GG 5
#define OO 2
#define TN 3     // nodes per k_social block

#define PI_OFF  0
#define MU_OFF  (NN*GG)              // 1920
#define SIG_OFF (MU_OFF + NN*GG*OO)  // 5760
#define H_OFF   (SIG_OFF + NN*GG*OO) // 9600
#define C_OFF   (H_OFF + NN*RR)      // 58752

// Scratch (no allocations allowed)
__device__ float g_P[NN*JJ];      // P[m][j] = dot(W_loc[j], nodes[m])
__device__ float g_X[NN*RR];      // x = relu(nodes[:,:4]@W_in^T + b_in) + social
__device__ float g_WT[256*JJ];    // transposed [X|H] weights: row k, col j
__device__ float g_Wmsum[KK];     // sum_r W_mode[r,k]
__device__ float g_bmsum[1];      // sum_r b_mode[r]

// ---------------------------------------------------------------------------
// K1: P[m][j] = dot6(W_loc[j], nodes[m]); 8 nodes per block.
// ---------------------------------------------------------------------------
__global__ void __launch_bounds__(512) k_pre(
    const float* __restrict__ nodes, const float* __restrict__ W_loc,
    const float* __restrict__ W_mode, const float* __restrict__ b_mode)
{
    int j = threadIdx.x;
    int m0 = blockIdx.x * 8;
    __shared__ float nd[8][6];
    if (j < 48) nd[j/6][j%6] = nodes[m0*6 + j];
    const float* w = W_loc + j*6;
    float w0 = w[0], w1 = w[1], w2 = w[2], w3 = w[3], w4 = w[4], w5 = w[5];
    __syncthreads();
    #pragma unroll
    for (int mm = 0; mm < 8; mm++) {
        g_P[(m0+mm)*JJ + j] = w0*nd[mm][0] + w1*nd[mm][1] + w2*nd[mm][2]
                            + w3*nd[mm][3] + w4*nd[mm][4] + w5*nd[mm][5];
    }

    if (blockIdx.x == 0 && j < 32) {
        float sk0=0.f, sk1=0.f, sk2=0.f, sk3=0.f, sbm=0.f;
        for (int r = j; r < RR; r += 32) {
            sk0 += W_mode[r*4+0];
            sk1 += W_mode[r*4+1];
            sk2 += W_mode[r*4+2];
            sk3 += W_mode[r*4+3];
            sbm += b_mode[r];
        }
        #pragma unroll
        for (int o = 16; o > 0; o >>= 1) {
            sk0 += __shfl_down_sync(0xffffffffu, sk0, o);
            sk1 += __shfl_down_sync(0xffffffffu, sk1, o);
            sk2 += __shfl_down_sync(0xffffffffu, sk2, o);
            sk3 += __shfl_down_sync(0xffffffffu, sk3, o);
            sbm += __shfl_down_sync(0xffffffffu, sbm, o);
        }
        if (j == 0) {
            g_Wmsum[0] = sk0; g_Wmsum[1] = sk1;
            g_Wmsum[2] = sk2; g_Wmsum[3] = sk3;
            g_bmsum[0] = sbm;
        }
    }
}

// ---------------------------------------------------------------------------
// K1b: transpose W_ih / W_hh into g_WT[k][j]  (k<128 -> W_ih, else W_hh).
// ---------------------------------------------------------------------------
__global__ void __launch_bounds__(256) k_wt(
    const float* __restrict__ W_ih, const float* __restrict__ W_hh)
{
    __shared__ float tile[32][33];
    int jb = blockIdx.x * 32;          // gridDim.x = 16
    int rb = blockIdx.y * 32;          // gridDim.y = 4
    const float* W = blockIdx.z ? W_hh : W_ih;
    int tx = threadIdx.x & 31;
    int ty = threadIdx.x >> 5;         // 0..7
    #pragma unroll
    for (int u = 0; u < 32; u += 8)
        tile[ty+u][tx] = W[(jb+ty+u)*RR + rb + tx];
    __syncthreads();
    int kbase = rb + blockIdx.z * RR;
    #pragma unroll
    for (int u = 0; u < 32; u += 8)
        g_WT[(kbase+ty+u)*JJ + jb + tx] = tile[tx][ty+u];
}

// ---------------------------------------------------------------------------
// K2: social attention, TN=3 nodes per block (128 blocks).
// ---------------------------------------------------------------------------
__global__ void __launch_bounds__(256) k_social(
    const float* __restrict__ nodes, const int* __restrict__ visible,
    const float* __restrict__ h_in,  const float* __restrict__ b_loc,
    const float* __restrict__ W_score, const float* __restrict__ b_score,
    const float* __restrict__ W_mode,  const float* __restrict__ b_mode,
    const float* __restrict__ W_in,    const float* __restrict__ b_in)
{
    int n0 = blockIdx.x * TN;
    int t = threadIdx.x;
    int lane = t & 31;
    int wrp  = t >> 5;

    __shared__ __align__(16) float sPn[TN][JJ];
    __shared__ __align__(16) float sb[JJ];
    __shared__ float shs[TN][RR];
    __shared__ float ssv[TN][NN];
    __shared__ float sal[TN][NN];
    __shared__ int   skh[TN][NN];     // -1 => invisible
    __shared__ float scoef[TN][NN];   // w_i * alpha_i
    __shared__ float sred[8*5];
    __shared__ float sm4[TN][KK], sden[TN][KK], sSk[TN][KK];
    __shared__ float sWtot[TN];
    __shared__ float sscal[8];        // [0]=b_score, [1..4]=Wmsum, [5]=bmsum
    __shared__ float snd[TN][6];
    __shared__ float sChalf[TN][RR];

    // preamble: g_P rows n0..n0+2 are contiguous
    for (int e = t; e < TN*JJ; e += 256) sPn[0][e] = g_P[n0*JJ + e];
    for (int e = t; e < JJ; e += 256)    sb[e] = b_loc[e];
    for (int e = t; e < TN*RR; e += 256)
        shs[0][e] = h_in[n0*RR + e] * W_score[e & 127];
    if (t == 0) sscal[0] = b_score[0];
    if (t < 4)  sscal[1+t] = g_Wmsum[t];
    if (t == 4) sscal[5] = g_bmsum[0];
    if (t < TN*6) snd[t/6][t%6] = nodes[n0*6 + t];
    __syncthreads();

    // --- Phase A: per pair i, shared row load for all TN nodes ---
    {
        int p   = lane >> 3;   // pair within warp (0..3)
        int sub = lane & 7;    // lane within pair
        const float4* B4 = (const float4*)sb;
        #pragma unroll 1
        for (int it = 0; it < 12; it++) {
            int i = it*32 + wrp*4 + p;
            const float4* Pi = (const float4*)(g_P + i*JJ);
            float s[TN][4], L[TN][4];
            #pragma unroll
            for (int nn = 0; nn < TN; nn++)
                #pragma unroll
                for (int k = 0; k < 4; k++) { s[nn][k] = 0.f; L[nn][k] = 0.f; }

            #pragma unroll
            for (int u = 0; u < 16; u++) {
                int r = sub + 8*u;
                float4 pi4 = Pi[r];
                float4 b4  = B4[r];
                float bx = b4.x - pi4.x;
                float by = b4.y - pi4.y;
                float bz = b4.z - pi4.z;
                float bw = b4.w - pi4.w;
                #pragma unroll
                for (int nn = 0; nn < TN; nn++) {
                    float4 pn4 = ((const float4*)sPn[nn])[r];
                    float hv = shs[nn][r];
                    float l0 = fmaxf(pn4.x + bx, 0.f);
                    float l1 = fmaxf(pn4.y + by, 0.f);
                    float l2 = fmaxf(pn4.z + bz, 0.f);
                    float l3 = fmaxf(pn4.w + bw, 0.f);
                    s[nn][0] += l0*hv; s[nn][1] += l1*hv;
                    s[nn][2] += l2*hv; s[nn][3] += l3*hv;
                    L[nn][0] += l0; L[nn][1] += l1;
                    L[nn][2] += l2; L[nn][3] += l3;
                }
            }
            #pragma unroll
            for (int o = 4; o > 0; o >>= 1) {
                #pragma unroll
                for (int nn = 0; nn < TN; nn++)
                    #pragma unroll
                    for (int k = 0; k < 4; k++) {
                        s[nn][k] += __shfl_xor_sync(0xffffffffu, s[nn][k], o);
                        L[nn][k] += __shfl_xor_sync(0xffffffffu, L[nn][k], o);
                    }
            }
            if (sub == 0) {
                float bs = sscal[0];
                #pragma unroll
                for (int nn = 0; nn < TN; nn++) {
                    float s0 = s[nn][0]+bs, s1 = s[nn][1]+bs;
                    float s2 = s[nn][2]+bs, s3 = s[nn][3]+bs;
                    int kh = 0; float smx = s0;
                    if (s1 > smx) { smx = s1; kh = 1; }
                    if (s2 > smx) { smx = s2; kh = 2; }
                    if (s3 > smx) { smx = s3; kh = 3; }
                    float e0 = __expf(s0 - smx), e1 = __expf(s1 - smx);
                    float e2 = __expf(s2 - smx), e3 = __expf(s3 - smx);
                    float soft = 1.0f / (e0 + e1 + e2 + e3);   // softmax @khat
                    float alpha = (1.0f - soft) + soft;        // straight-through
                    float Lh = (kh==0) ? L[nn][0] : (kh==1) ? L[nn][1]
                             : (kh==2) ? L[nn][2] : L[nn][3];
                    float sv = alpha*Lh + (alpha*sscal[1+kh] + sscal[5]);
                    int vis = visible[(n0+nn)*NN + i];
                    skh[nn][i] = (vis > 0) ? kh : -1;
                    sal[nn][i] = alpha;
                    ssv[nn][i] = sv;
                }
            }
        }
    }
    __syncthreads();

    // --- Phase B: per-head masked softmax over neighbors, per node ---
    for (int nn = 0; nn < TN; nn++) {
        {   // pass 1: max per head
            float m0=-3.0e38f, m1=-3.0e38f, m2=-3.0e38f, m3=-3.0e38f;
            for (int i = t; i < NN; i += 256) {
                int kh = skh[nn][i];
                float v = ssv[nn][i];
                if (kh == 0) m0 = fmaxf(m0, v);
                else if (kh == 1) m1 = fmaxf(m1, v);
                else if (kh == 2) m2 = fmaxf(m2, v);
                else if (kh == 3) m3 = fmaxf(m3, v);
            }
            #pragma unroll
            for (int o = 16; o > 0; o >>= 1) {
                m0 = fmaxf(m0, __shfl_xor_sync(0xffffffffu, m0, o));
                m1 = fmaxf(m1, __shfl_xor_sync(0xffffffffu, m1, o));
                m2 = fmaxf(m2, __shfl_xor_sync(0xffffffffu, m2, o));
                m3 = fmaxf(m3, __shfl_xor_sync(0xffffffffu, m3, o));
            }
            if (lane == 0) {
                sred[wrp*4+0]=m0; sred[wrp*4+1]=m1;
                sred[wrp*4+2]=m2; sred[wrp*4+3]=m3;
            }
            __syncthreads();
            if (t < 4) {
                float m = sred[t];
                for (int ww = 1; ww < 8; ww++) m = fmaxf(m, sred[ww*4+t]);
                sm4[nn][t] = m;
            }
            __syncthreads();
        }
        {   // pass 2: denominators
            float d0=0.f, d1=0.f, d2=0.f, d3=0.f;
            for (int i = t; i < NN; i += 256) {
                int kh = skh[nn][i];
                if (kh >= 0) {
                    float e = __expf(ssv[nn][i] - sm4[nn][kh]);
                    if (kh == 0) d0 += e;
                    else if (kh == 1) d1 += e;
                    else if (kh == 2) d2 += e;
                    else d3 += e;
                }
            }
            #pragma unroll
            for (int o = 16; o > 0; o >>= 1) {
                d0 += __shfl_xor_sync(0xffffffffu, d0, o);
                d1 += __shfl_xor_sync(0xffffffffu, d1, o);
                d2 += __shfl_xor_sync(0xffffffffu, d2, o);
                d3 += __shfl_xor_sync(0xffffffffu, d3, o);
            }
            if (lane == 0) {
                sred[wrp*4+0]=d0; sred[wrp*4+1]=d1;
                sred[wrp*4+2]=d2; sred[wrp*4+3]=d3;
            }
            __syncthreads();
            if (t < 4) {
                float d = 0.f;
                for (int ww = 0; ww < 8; ww++) d += sred[ww*4+t];
                sden[nn][t] = d;
            }
            __syncthreads();
        }
        {   // pass 3: coefficients + group sums
            float k0=0.f, k1=0.f, k2=0.f, k3=0.f, wt=0.f;
            for (int i = t; i < NN; i += 256) {
                int kh = skh[nn][i];
                float c = 0.f;
                if (kh >= 0) {
                    float wv = __expf(ssv[nn][i] - sm4[nn][kh]) / sden[nn][kh];
                    c = wv * sal[nn][i];
                    wt += wv;
                    if (kh == 0) k0 += c;
                    else if (kh == 1) k1 += c;
                    else if (kh == 2) k2 += c;
                    else k3 += c;
                }
                scoef[nn][i] = c;
            }
            #pragma unroll
            for (int o = 16; o > 0; o >>= 1) {
                k0 += __shfl_xor_sync(0xffffffffu, k0, o);
                k1 += __shfl_xor_sync(0xffffffffu, k1, o);
                k2 += __shfl_xor_sync(0xffffffffu, k2, o);
                k3 += __shfl_xor_sync(0xffffffffu, k3, o);
                wt += __shfl_xor_sync(0xffffffffu, wt, o);
            }
            if (lane == 0) {
                sred[wrp*5+0]=k0; sred[wrp*5+1]=k1; sred[wrp*5+2]=k2;
                sred[wrp*5+3]=k3; sred[wrp*5+4]=wt;
            }
            __syncthreads();
            if (t < 5) {
                float s = 0.f;
                for (int ww = 0; ww < 8; ww++) s += sred[ww*5+t];
                if (t < 4) sSk[nn][t] = s; else sWtot[nn] = s;
            }
            __syncthreads();
        }
    }

    // --- Phase C: accumulate for all TN nodes while streaming rows ---
    {
        int r = t & 127;
        int half = t >> 7;
        float acc[TN];
        #pragma unroll
        for (int nn = 0; nn < TN; nn++) acc[nn] = 0.f;
        int i0 = half * 192;
        #pragma unroll 2
        for (int i = i0; i < i0 + 192; i++) {
            const float* Prow = g_P + i*JJ + r*4;
            #pragma unroll
            for (int nn = 0; nn < TN; nn++) {
                int kh = skh[nn][i];
                float c = scoef[nn][i];
                if (kh >= 0 && c != 0.f) {
                    int j = r*4 + kh;
                    acc[nn] += c * fmaxf(sPn[nn][j] - Prow[kh] + sb[j], 0.f);
                }
            }
        }
        if (half == 1) {
            #pragma unroll
            for (int nn = 0; nn < TN; nn++) sChalf[nn][r] = acc[nn];
        }
        __syncthreads();
        if (half == 0) {
            #pragma unroll
            for (int nn = 0; nn < TN; nn++) {
                float a = acc[nn] + sChalf[nn][r];
                float soc = a
                    + sSk[nn][0]*W_mode[r*4+0] + sSk[nn][1]*W_mode[r*4+1]
                    + sSk[nn][2]*W_mode[r*4+2] + sSk[nn][3]*W_mode[r*4+3]
                    + sWtot[nn] * b_mode[r];
                const float* wi = W_in + r*4;
                float xr = fmaxf(wi[0]*snd[nn][0] + wi[1]*snd[nn][1]
                               + wi[2]*snd[nn][2] + wi[3]*snd[nn][3]
                               + b_in[r], 0.f) + soc;
                g_X[(n0+nn)*RR + r] = xr;
            }
        }
    }
}

// ---------------------------------------------------------------------------
// K3: LSTM cell as GEMM (double-buffered W prefetch) + MDN heads. 4 nodes/blk.
// ---------------------------------------------------------------------------
__device__ __forceinline__ float sigf(float x) { return 1.f / (1.f + __expf(-x)); }

#define BN 4
__global__ void __launch_bounds__(256) k_lstm(
    const float* __restrict__ h_in, const float* __restrict__ c_in,
    const float* __restrict__ b_ih, const float* __restrict__ b_hh,
    const float* __restrict__ W_pi, const float* __restrict__ b_pi,
    const float* __restrict__ W_mu, const float* __restrict__ b_mu,
    const float* __restrict__ W_sig, const float* __restrict__ b_sig,
    float* __restrict__ out)
{
    int n0 = blockIdx.x * BN;
    int t = threadIdx.x;

    __shared__ float sA[BN][256];   // [nn][k] : X (k<128) then H
    __shared__ float sG[BN][JJ];
    __shared__ float sW[25*RR];
    __shared__ float sh[BN][RR];
    __shared__ float sLg[BN][25];

    for (int e = t; e < BN*RR; e += 256) {
        int nn = e >> 7, r = e & 127;
        sA[nn][r]     = g_X[(n0+nn)*RR + r];
        sA[nn][128+r] = h_in[(n0+nn)*RR + r];
    }
    for (int e = t; e < 25*RR; e += 256) {
        float v = (e < 640) ? W_pi[e] : (e < 1920) ? W_mu[e-640] : W_sig[e-1920];
        sW[e] = v;
    }
    __syncthreads();

    // gates for columns j0=2t, j1=2t+1 over 4 nodes; prefetched W (MLP=8)
    int j0 = 2*t, j1 = 2*t + 1;
    float a0[BN] = {0.f,0.f,0.f,0.f};
    float a1[BN] = {0.f,0.f,0.f,0.f};
    const float2* WT2 = (const float2*)g_WT;
    float2 wb0[8];
    #pragma unroll
    for (int u = 0; u < 8; u++) wb0[u] = WT2[u*256 + t];
    #pragma unroll 1
    for (int kt = 0; kt < 256; kt += 8) {
        float2 wb1[8];
        int kn = kt + 8;
        if (kn < 256) {
            #pragma unroll
            for (int u = 0; u < 8; u++) wb1[u] = WT2[(kn+u)*256 + t];
        }
        #pragma unroll
        for (int u = 0; u < 8; u++) {
            float wx = wb0[u].x, wy = wb0[u].y;
            #pragma unroll
            for (int nn = 0; nn < BN; nn++) {
                float a = sA[nn][kt+u];
                a0[nn] = fmaf(a, wx, a0[nn]);
                a1[nn] = fmaf(a, wy, a1[nn]);
            }
        }
        #pragma unroll
        for (int u = 0; u < 8; u++) wb0[u] = wb1[u];
    }
    float bb0 = b_ih[j0] + b_hh[j0];
    float bb1 = b_ih[j1] + b_hh[j1];
    #pragma unroll
    for (int nn = 0; nn < BN; nn++) {
        sG[nn][j0] = a0[nn] + bb0;
        sG[nn][j1] = a1[nn] + bb1;
    }
    __syncthreads();

    // LSTM combine; write h,c
    for (int e = t; e < BN*RR; e += 256) {
        int nn = e >> 7, r = e & 127;
        float gi = sG[nn][r];
        float gf = sG[nn][RR + r];
        float gg = sG[nn][2*RR + r];
        float go = sG[nn][3*RR + r];
        float cp = c_in[(n0+nn)*RR + r];
        float c = sigf(gf)*cp + sigf(gi)*tanhf(gg);
        float h = sigf(go)*tanhf(c);
        out[C_OFF + (n0+nn)*RR + r] = c;
        out[H_OFF + (n0+nn)*RR + r] = h;
        sh[nn][r] = h;
    }
    __syncthreads();

    // heads: 25 dot products per node
    if (t < BN*25) {
        int nn = t / 25, q = t % 25;
        const float* wr = sW + q*RR;
        float acc = 0.f;
        #pragma unroll 4
        for (int r = 0; r < RR; r++) acc += wr[r] * sh[nn][r];
        sLg[nn][q] = acc;
    }
    __syncthreads();

    if (t < BN) {  // pi softmax
        int nn = t;
        float l[GG];
        float m = -3.0e38f;
        #pragma unroll
        for (int g = 0; g < GG; g++) { l[g] = sLg[nn][g] + b_pi[g]; m = fmaxf(m, l[g]); }
        float s = 0.f;
        #pragma unroll
        for (int g = 0; g < GG; g++) { l[g] = __expf(l[g] - m); s += l[g]; }
        float inv = 1.f / s;
        #pragma unroll
        for (int g = 0; g < GG; g++)
            out[PI_OFF + (n0+nn)*GG + g] = l[g] * inv;
    }
    if (t >= 32 && t < 32 + BN*10) {  // mu
        int idx = t - 32;
        int nn = idx / 10, q = idx % 10;
        out[MU_OFF + (n0+nn)*10 + q] = sLg[nn][5+q] + b_mu[q];
    }
    if (t >= 96 && t < 96 + BN*10) {  // sigma
        int idx = t - 96;
        int nn = idx / 10, q = idx % 10;
        out[SIG_OFF + (n0+nn)*10 + q] = __expf(sLg[nn][15+q] + b_sig[q]);
    }
}

// ---------------------------------------------------------------------------
extern "C" void kernel_launch(void* const* d_in, const int* in_sizes, int n_in,
                              void* d_out, int out_size)
{
    const float* nodes   = (const float*)d_in[0];
    const int*   visible = (const int*)  d_in[1];
    const float* h_in    = (const float*)d_in[2];
    const float* c_in    = (const float*)d_in[3];
    const float* W_loc   = (const float*)d_in[4];
    const float* b_loc   = (const float*)d_in[5];
    const float* W_score = (const float*)d_in[6];
    const float* b_score = (const float*)d_in[7];
    const float* W_mode  = (const float*)d_in[8];
    const float* b_mode  = (const float*)d_in[9];
    const float* W_in    = (const float*)d_in[10];
    const float* b_in    = (const float*)d_in[11];
    const float* W_ih    = (const float*)d_in[12];
    const float* W_hh    = (const float*)d_in[13];
    const float* b_ih    = (const float*)d_in[14];
    const float* b_hh    = (const float*)d_in[15];
    const float* W_pi    = (const float*)d_in[16];
    const float* b_pi    = (const float*)d_in[17];
    const float* W_mu    = (const float*)d_in[18];
    const float* b_mu    = (const float*)d_in[19];
    const float* W_sig   = (const float*)d_in[20];
    const float* b_sig   = (const float*)d_in[21];
    float* out = (float*)d_out;

    k_pre<<<NN/8, 512>>>(nodes, W_loc, W_mode, b_mode);
    dim3 wt_grid(16, 4, 2);
    k_wt<<<wt_grid, 256>>>(W_ih, W_hh);
    k_social<<<NN/TN, 256>>>(nodes, visible, h_in, b_loc, W_score, b_score,
                             W_mode, b_mode, W_in, b_in);
    k_lstm<<<NN/BN, 256>>>(h_in, c_in, b_ih, b_hh,
                           W_pi, b_pi, W_mu, b_mu, W_sig, b_sig, out);
}